// round 17
// baseline (speedup 1.0000x reference)
#include <cuda_runtime.h>
#include <math.h>
#include <stdint.h>

#define NT 365
#define NS 2048
#define NH 64
#define NG 128
#define NW 513   // NH*8+1

#define GEMM_BLOCKS 896                       // 64 site-tiles x 14 used j-tiles
#define PART_BLOCKS ((NT * NS + 255) / 256)   // 2920

// ---------------- scratch (static device globals; no allocation) -------------
__device__ float4 g_flux[(NT + 16) * NS];  // [t][s] = {ps, pl, e, relu(Ta)}; padded
__device__ float  g_w[(size_t)NS * 512];   // fc output w[s][j] (slice j=128..191 unused)

__device__ __forceinline__ float sigmoidf_(float x) {
    return 1.0f / (1.0f + expf(-x));
}

// ---------------- kernel A: fused rain/snow partition + GEMM ------------------
__global__ void __launch_bounds__(256) k_pre(const float4* __restrict__ x,
                                             const float* __restrict__ xc,
                                             const float* __restrict__ W,
                                             const float* __restrict__ b) {
    __shared__ float xs[32 * 132];   // [site][c], padded stride
    __shared__ float ws[32 * 128];   // [j_local][c]
    int tid = threadIdx.x;

    if (blockIdx.x < GEMM_BLOCKS) {
        int s0 = (blockIdx.x & 63) << 5;      // 64 site-tiles
        int jt = blockIdx.x >> 6;             // 0..13 used j-tiles
        int jbase = (jt << 5) + (jt >= 4 ? 64 : 0);  // skip j=128..191

        for (int idx = tid; idx < 32 * NG; idx += 256) {
            int sl = idx >> 7, c = idx & (NG - 1);
            xs[sl * 132 + c] = xc[(size_t)(s0 + sl) * NG + c];
        }
        {
            const float4* Wt = (const float4*)(W + (size_t)jbase * NG);
            float4* ws4 = (float4*)ws;
            for (int idx = tid; idx < 32 * NG / 4; idx += 256)
                ws4[idx] = Wt[idx];
        }
        __syncthreads();

        int sl = tid & 31;
        int joff = tid >> 5;
        float acc[4] = {0.f, 0.f, 0.f, 0.f};
        const float4* xv4 = (const float4*)&xs[sl * 132];
        const float4* wr0 = (const float4*)&ws[(joff +  0) * NG];
        const float4* wr1 = (const float4*)&ws[(joff +  8) * NG];
        const float4* wr2 = (const float4*)&ws[(joff + 16) * NG];
        const float4* wr3 = (const float4*)&ws[(joff + 24) * NG];

#pragma unroll 8
        for (int c4 = 0; c4 < NG / 4; ++c4) {
            float4 xv = xv4[c4];
            float4 w0 = wr0[c4], w1 = wr1[c4], w2 = wr2[c4], w3 = wr3[c4];
            acc[0] += xv.x * w0.x + xv.y * w0.y + xv.z * w0.z + xv.w * w0.w;
            acc[1] += xv.x * w1.x + xv.y * w1.y + xv.z * w1.z + xv.w * w1.w;
            acc[2] += xv.x * w2.x + xv.y * w2.y + xv.z * w2.z + xv.w * w2.w;
            acc[3] += xv.x * w3.x + xv.y * w3.y + xv.z * w3.z + xv.w * w3.w;
        }
#pragma unroll
        for (int i = 0; i < 4; i++) {
            int j = jbase + joff + i * 8;
            g_w[(size_t)(s0 + sl) * 512 + j] = acc[i] + b[j];
        }
    } else {
        int i = (blockIdx.x - GEMM_BLOCKS) * 256 + tid;
        if (i >= NT * NS) return;
        float4 v = x[i];
        float P = v.x, E = v.y, T1 = v.z, T2 = v.w;
        float Ta = 0.5f * (T1 + T2);
        float rP;
        if (T1 >= 0.0f)      rP = 1.0f;
        else if (T2 <= 0.0f) rP = 0.0f;
        else                 rP = 1.0f - acosf(__fdividef(T1 + T2, T2 - T1)) / 3.1415f;
        float pl = rP * P;
        float ps = (1.0f - rP) * P;
        g_flux[i] = make_float4(ps, pl, E, fmaxf(Ta, 0.0f));
    }
}

// ---------------- kernel B: fused params + sequential scan --------------------
// 1 warp per site (2048 warps). 16-step ping-pong (fA/fB, yA/yB); each lane
// carries two independent scalar chains (h = lane, h = lane+32). Reduction of
// block i is software-pipelined into block i+1 via a HALVING TREE
// (16 SHFL + 16 FADD + 7 SEL per 8 steps); lane L ends holding the complete
// sum for step L&7, so lanes 0..7 store through a running output pointer.
__global__ void __launch_bounds__(64) k_scan(float* __restrict__ out,
                                             const float* __restrict__ xc,
                                             const float* __restrict__ W,
                                             const float* __restrict__ b) {
    int lane = threadIdx.x & 31;
    int s = blockIdx.x * 2 + (threadIdx.x >> 5);
    const bool b1 = (lane & 1) != 0;
    const bool b2 = (lane & 2) != 0;
    const bool b4 = (lane & 4) != 0;

    // ================= prologue: params in registers =================
    const float* wr = g_w + (size_t)s * 512;
    int hA = lane, hB = lane + 32;
    float wgmA = wr[0 * NH + hA], wgmB = wr[0 * NH + hB];
    float wgeA = wr[1 * NH + hA], wgeB = wr[1 * NH + hB];
    float wk0A = wr[3 * NH + hA], wk0B = wr[3 * NH + hB];
    float wk1A = wr[4 * NH + hA], wk1B = wr[4 * NH + hB];
    float wk2A = wr[5 * NH + hA], wk2B = wr[5 * NH + hB];
    float wglA = wr[6 * NH + hA], wglB = wr[6 * NH + hB];
    float wkbA = wr[7 * NH + hA], wkbB = wr[7 * NH + hB];

    // w512 = xc[s]·W[512] + b[512]
    float p = 0.f;
    const float* w512row = W + 512 * NG;
    const float* xcr = xc + (size_t)s * NG;
#pragma unroll
    for (int k = 0; k < 4; k++)
        p = fmaf(xcr[lane + 32 * k], w512row[lane + 32 * k], p);
#pragma unroll
    for (int o = 16; o; o >>= 1) p += __shfl_xor_sync(0xffffffffu, p, o);
    float w512 = p + b[512];
    float vi = sigmoidf_(w512);
    float qb = fmaxf(w512, 0.f) / (float)NH;

    // softmax over the k1 pre-activation slice (64 values across the warp)
    float mx = fmaxf(wk1A, wk1B);
#pragma unroll
    for (int o = 16; o; o >>= 1) mx = fmaxf(mx, __shfl_xor_sync(0xffffffffu, mx, o));
    float eA = expf(wk1A - mx), eB = expf(wk1B - mx);
    float sum = eA + eB;
#pragma unroll
    for (int o = 16; o; o >>= 1) sum += __shfl_xor_sync(0xffffffffu, sum, o);
    float inv = 1.0f / sum;
    float gaA = eA * inv, gaB = eB * inv;

    float k0A = sigmoidf_(wk0A),          k0B = sigmoidf_(wk0B);
    float k1A = sigmoidf_(wk1A),          k1B = sigmoidf_(wk1B);
    float k2A = sigmoidf_(wk2A),          k2B = sigmoidf_(wk2B);
    float kbA = sigmoidf_(wkbA) / 10.0f,  kbB = sigmoidf_(wkbB) / 10.0f;
    float kkbA = k1A * kbA,               kkbB = k1B * kbB;

    float2 gm    = make_float2(expf(wgmA) + 1.0f,       expf(wgmB) + 1.0f);
    float2 nge   = make_float2(-2.0f * sigmoidf_(wgeA), -2.0f * sigmoidf_(wgeB));
    float2 gl    = make_float2(expf(wglA),              expf(wglB));
    float2 ngl   = make_float2(-gl.x,                   -gl.y);
    float2 k0m   = make_float2(1.0f - k0A,              1.0f - k0B);
    float2 k0ga  = make_float2(k0A * gaA,               k0B * gaB);
    float2 nk1   = make_float2(-k1A,                    -k1B);
    float2 k2m   = make_float2(1.0f - k2A,              1.0f - k2B);
    float2 k2ga  = make_float2(k2A * gaA,               k2B * gaB);
    float2 kd    = make_float2(kkbA * k2m.x,            kkbB * k2m.y);
    float2 kq1c  = make_float2(k1A * (1.0f - kbA) * gaA + kkbA * k2ga.x,
                               k1B * (1.0f - kbB) * gaB + kkbB * k2ga.y);

    // ================= main loop =================
    float S0A = 0.f, H0A = ngl.x, H1A = 0.f, H2A = 0.f;
    float S0B = 0.f, H0B = ngl.y, H1B = 0.f, H2B = 0.f;
    float4 fA[8], fB[8];
    float yA[8], yB[8];
    float z0, z1, z2, z3, w0, w1, qv;

    float* pout = out + s;                       // running store pointer (row 0)
    const size_t loff = (size_t)lane * NS;       // per-lane store offset (lanes 0..7)

#define STEP(F, Y, K)                                                          \
    {                                                                          \
        float ps = (F).x, pl = (F).y, e = (F).z, tap = (F).w;                  \
        float plvi = pl * vi;                                                  \
        float plv1 = pl - plvi;                                                \
        float amA = tap * gm.x;                                                \
        float SmA = fminf(S0A, amA);                                           \
        S0A = (S0A - SmA) + ps;                                                \
        float G1A = fmaxf((H1A + SmA) + fmaf(e, nge.x, plvi), 0.f);            \
        float G0A = fmaxf((H0A + G1A) + plv1, 0.f);                            \
        H0A = fmaf(G0A, k0m.x, ngl.x);                                         \
        float yAv = G0A * k0ga.x;                                              \
        float m1A = fminf(G1A, gl.x);                                          \
        H1A = fminf(fmaf(m1A, nk1.x, G1A), gl.x);                              \
        yAv = fmaf(H2A, k2ga.x, yAv);                                          \
        yAv = fmaf(m1A, kq1c.x, yAv);                                          \
        float h2tA = H2A * k2m.x;                                              \
        H2A = fmaf(m1A, kd.x, h2tA);                                           \
        float amB = tap * gm.y;                                                \
        float SmB = fminf(S0B, amB);                                           \
        S0B = (S0B - SmB) + ps;                                                \
        float G1B = fmaxf((H1B + SmB) + fmaf(e, nge.y, plvi), 0.f);            \
        float G0B = fmaxf((H0B + G1B) + plv1, 0.f);                            \
        H0B = fmaf(G0B, k0m.y, ngl.y);                                         \
        float yBv = G0B * k0ga.y;                                              \
        float m1B = fminf(G1B, gl.y);                                          \
        H1B = fminf(fmaf(m1B, nk1.y, G1B), gl.y);                              \
        yBv = fmaf(H2B, k2ga.y, yBv);                                          \
        yBv = fmaf(m1B, kq1c.y, yBv);                                          \
        float h2tB = H2B * k2m.y;                                              \
        H2B = fmaf(m1B, kd.y, h2tB);                                           \
        (Y)[K] = yAv + yBv;                                                    \
    }

#define SH(v, o) __shfl_xor_sync(0xffffffffu, (v), (o))
    // halving-tree reduction of 8 deferred values, spread over 8 STEPs
#define R_A(Y) { (Y)[0]+=SH((Y)[0],1); (Y)[1]+=SH((Y)[1],1);                   \
                 (Y)[2]+=SH((Y)[2],1); (Y)[3]+=SH((Y)[3],1); }
#define R_B(Y) { (Y)[4]+=SH((Y)[4],1); (Y)[5]+=SH((Y)[5],1);                   \
                 (Y)[6]+=SH((Y)[6],1); (Y)[7]+=SH((Y)[7],1); }
#define R_C(Y) { z0 = b1 ? (Y)[1] : (Y)[0]; z1 = b1 ? (Y)[3] : (Y)[2];         \
                 z2 = b1 ? (Y)[5] : (Y)[4]; z3 = b1 ? (Y)[7] : (Y)[6];         \
                 z0 += SH(z0,2); z1 += SH(z1,2); }
#define R_D() { z2 += SH(z2,2); z3 += SH(z3,2); }
#define R_E() { w0 = b2 ? z1 : z0; w1 = b2 ? z3 : z2;                          \
                w0 += SH(w0,4); w1 += SH(w1,4); }
#define R_F() { qv = b4 ? w1 : w0; qv += SH(qv,8); }
#define R_G() { qv += SH(qv,16); }
#define R_ST() { if (lane < 8) pout[loff] = qv + qb; pout += (size_t)8 * NS; }

    // one 8-step block: STEP into YCUR from FCUR, reduce+store YPREV
#define BLOCK8(FCUR, YCUR, YPREV)                                              \
    STEP(FCUR[0], YCUR, 0)  R_A(YPREV)                                         \
    STEP(FCUR[1], YCUR, 1)  R_B(YPREV)                                         \
    STEP(FCUR[2], YCUR, 2)  R_C(YPREV)                                         \
    STEP(FCUR[3], YCUR, 3)  R_D()                                              \
    STEP(FCUR[4], YCUR, 4)  R_E()                                              \
    STEP(FCUR[5], YCUR, 5)  R_F()                                              \
    STEP(FCUR[6], YCUR, 6)  R_G()                                              \
    STEP(FCUR[7], YCUR, 7)  R_ST()

#define LOADBLK(DST)                                                           \
    {                                                                          \
        _Pragma("unroll")                                                      \
        for (int k = 0; k < 8; k++) DST[k] = pn[(size_t)k * NS];               \
        pn += (size_t)8 * NS;                                                  \
    }

    const float4* pn = g_flux + s;

    // preload fA = rows 0..7; block 0: load fB (rows 8..15), STEP fA -> yA
    LOADBLK(fA)
    LOADBLK(fB)
    STEP(fA[0], yA, 0) STEP(fA[1], yA, 1) STEP(fA[2], yA, 2) STEP(fA[3], yA, 3)
    STEP(fA[4], yA, 4) STEP(fA[5], yA, 5) STEP(fA[6], yA, 6) STEP(fA[7], yA, 7)

    // 22 pairs: blocks 1..44 (t = 8..359), reducing/storing the previous block
    for (int pr = 0; pr < 22; ++pr) {
        LOADBLK(fA)                      // rows for block 2pr+2
        BLOCK8(fB, yB, yA)               // compute block 2pr+1, store block 2pr
        LOADBLK(fB)                      // rows for block 2pr+3
        BLOCK8(fA, yA, yB)               // compute block 2pr+2, store block 2pr+1
    }

    // drain block 44 reduction (t = 352..359); yA holds it
    R_A(yA) R_B(yA) R_C(yA) R_D() R_E() R_F() R_G() R_ST()

    // epilogue: t = 360..364 (fB holds rows 360..367)
#pragma unroll
    for (int k = 0; k < 5; k++) {
        STEP(fB[k], yA, 0)
        float r = yA[0];
#pragma unroll
        for (int o = 16; o; o >>= 1) r += __shfl_xor_sync(0xffffffffu, r, o);
        if (lane == 0) out[(size_t)(360 + k) * NS + s] = r + qb;
    }
#undef STEP
#undef SH
#undef R_A
#undef R_B
#undef R_C
#undef R_D
#undef R_E
#undef R_F
#undef R_G
#undef R_ST
#undef BLOCK8
#undef LOADBLK
}

// ---------------- launch ------------------------------------------------------
extern "C" void kernel_launch(void* const* d_in, const int* in_sizes, int n_in,
                              void* d_out, int out_size) {
    const float* x  = (const float*)d_in[0];  // [NT, NS, 4]
    const float* xc = (const float*)d_in[1];  // [NS, NG]
    const float* W  = (const float*)d_in[2];  // [NW, NG]
    const float* b  = (const float*)d_in[3];  // [NW]
    float* out = (float*)d_out;               // [NT, NS]

    k_pre<<<GEMM_BLOCKS + PART_BLOCKS, 256>>>((const float4*)x, xc, W, b);
    k_scan<<<NS / 2, 64>>>(out, xc, W, b);   // fused params + scan
}